// round 15
// baseline (speedup 1.0000x reference)
#include <cuda_runtime.h>
#include <cuda_fp16.h>
#include <math.h>
#include <stdint.h>

#define BATCH 8
#define CI 512
#define CO 512
#define FH 50
#define FW 76
#define P 3800           // FH*FW
#define PPAD 3840        // padded pixels per image
#define NA 34200         // P*9
#define KD 4608          // 9*CI  (K order: r*512 + ci)
#define NSORT 65536
#define PRE 6000
#define POST 300
#define NSEL 8192

#define OFF_LOCS   0
#define OFF_SCORES 1094400
#define OFF_ROIS   1641600
#define OFF_ANCH   1651200

// ---------------- device scratch ----------------
__device__ float g_feat[BATCH*CO*P];
__device__ float g_roi[BATCH*NA*4];
__device__ float g_key[BATCH*NSORT];
__device__ int   g_idx[BATCH*NSORT];

__device__ __align__(16) __half g_w1h[CO*KD];
__device__ __align__(16) __half g_w2h[CO*KD];
__device__ __align__(16) __half g_x1T[(size_t)BATCH*PPAD*CI];
__device__ __align__(16) __half g_x2T[(size_t)BATCH*PPAD*CI];

// ---------------- helpers ----------------
__device__ __forceinline__ uint32_t smem_u32(const void* p){
    uint32_t a;
    asm("{ .reg .u64 t; cvta.to.shared.u64 t, %1; cvt.u32.u64 %0, t; }" : "=r"(a) : "l"(p));
    return a;
}
#define CP16(dst, src)       asm volatile("cp.async.cg.shared.global [%0], [%1], 16;" :: "r"(dst), "l"(src))
#define CP16Z(dst, src, sz)  asm volatile("cp.async.cg.shared.global [%0], [%1], 16, %2;" :: "r"(dst), "l"(src), "r"(sz))
#define CP_COMMIT()          asm volatile("cp.async.commit_group;" ::: "memory")
#define CP_WAIT1()           asm volatile("cp.async.wait_group 1;" ::: "memory")

#define MMA16816(d, a, b) asm volatile( \
    "mma.sync.aligned.m16n8k16.row.col.f32.f16.f16.f32 " \
    "{%0,%1,%2,%3}, {%4,%5,%6,%7}, {%8,%9}, {%0,%1,%2,%3};" \
    : "+f"((d)[0]), "+f"((d)[1]), "+f"((d)[2]), "+f"((d)[3]) \
    : "r"((a)[0]), "r"((a)[1]), "r"((a)[2]), "r"((a)[3]), \
      "r"((b)[0]), "r"((b)[1]))

#define LDSM4(r, a) asm volatile( \
    "ldmatrix.sync.aligned.m8n8.x4.shared.b16 {%0,%1,%2,%3}, [%4];" \
    : "=r"((r)[0]), "=r"((r)[1]), "=r"((r)[2]), "=r"((r)[3]) : "r"(a))

// ---------------- fused: weight split+reorder + anchors ----------------
#define N_WCVT (CO*KD)
#define N_ANCH NA
#define N_FUSE1 (N_WCVT + N_ANCH)

__global__ void fuse1_kernel(const float* __restrict__ w, float* __restrict__ out)
{
    int t = blockIdx.x*256 + threadIdx.x;
    if (t < N_WCVT) {
        int co = t / KD;
        int k  = t - co*KD;
        int r  = k >> 9;
        int ci = k & 511;
        float v = w[co*KD + ci*9 + r];
        __half h1 = __float2half_rn(v);
        float rr = v - __half2float(h1);
        __half h2 = __float2half_rn(rr * 4096.f);
        g_w1h[t] = h1; g_w2h[t] = h2;
        return;
    }
    int t2 = t - N_WCVT;
    if (t2 < N_ANCH) {
        int i = t2;
        int p = i / 9, a = i - p*9;
        int y = p / FW, x = p - y*FW;
        const float ratios[3] = {0.5f, 1.f, 2.f};
        const float scales[3] = {8.f, 16.f, 32.f};
        float r  = ratios[a/3];
        float sc = scales[a%3];
        float hh = 16.f * sc * sqrtf(r);
        float ww = 16.f * sc * sqrtf(1.f/r);
        float sx = x * 16.f, sy = y * 16.f;
        float* o = out + OFF_ANCH + (size_t)i*4;
        o[0] = sx + 8.f - ww*0.5f; o[1] = sy + 8.f - hh*0.5f;
        o[2] = sx + 8.f + ww*0.5f; o[3] = sy + 8.f + hh*0.5f;
    }
}

// ---------------- transpose x -> channel-last fp16 hi/lo ----------------
__global__ __launch_bounds__(256) void xpose_kernel(const float* __restrict__ x)
{
    __shared__ float sx[32][65];
    int px0 = blockIdx.x * 64;
    int ci0 = blockIdx.y * 32;
    int n   = blockIdx.z;
    int tid = threadIdx.x;

#pragma unroll
    for (int l = 0; l < 8; ++l) {
        int idx = tid + l*256;
        int row = idx >> 6, col = idx & 63;
        int gp = px0 + col;
        sx[row][col] = (gp < P) ? x[((size_t)n*CI + ci0 + row)*P + gp] : 0.f;
    }
    __syncthreads();

    int px_l = tid >> 2;
    int g    = tid & 3;
    float v[8];
#pragma unroll
    for (int q = 0; q < 8; ++q) v[q] = sx[g*8 + q][px_l];

    __half2 h1[4], h2[4];
#pragma unroll
    for (int j = 0; j < 4; ++j) {
        h1[j] = __floats2half2_rn(v[2*j], v[2*j+1]);
        float r0 = (v[2*j]   - __low2float(h1[j]))  * 4096.f;
        float r1 = (v[2*j+1] - __high2float(h1[j])) * 4096.f;
        h2[j] = __floats2half2_rn(r0, r1);
    }
    size_t o = ((size_t)n*PPAD + px0 + px_l)*CI + ci0 + g*8;
    *(uint4*)(g_x1T + o) = *(const uint4*)h1;
    *(uint4*)(g_x2T + o) = *(const uint4*)h2;
}

// ---------------- conv1: implicit im2col, KC=32, 3-stage single-barrier ----------------
#define KC 32
#define NSTG 144              // KD / KC ; stage it: r = it>>4, ci0 = (it&15)*32
#define A_SP 5120             // halves per A split: 128 rows x 40
#define B_SP 2560             // halves per B split: 64 rows x 40
#define STAGE_H 15360         // A1 A2 B1 B2
#define SMEM_CONV (3*STAGE_H*2)   // 92160 B

__global__ __launch_bounds__(256, 2) void conv_mma_kernel(const float* __restrict__ bias)
{
    extern __shared__ __half sh[];
    uint32_t sbase = smem_u32(sh);

    int tid  = threadIdx.x;
    int wid  = tid >> 5;
    int lane = tid & 31;
    int nimg = blockIdx.z;
    int co0  = blockIdx.x * 128;
    int px0  = blockIdx.y * 64;

    int wm = (wid & 3) * 32;
    int wn = (wid >> 2) * 32;
    int r0 = lane >> 2;

    float acc1[2][4][4], acc2[2][4][4];
#pragma unroll
    for (int mt = 0; mt < 2; ++mt)
#pragma unroll
        for (int nt = 0; nt < 4; ++nt)
#pragma unroll
            for (int c = 0; c < 4; ++c) { acc1[mt][nt][c] = 0.f; acc2[mt][nt][c] = 0.f; }

    const __half* w1b = g_w1h + (size_t)co0 * KD;
    const __half* w2b = g_w2h + (size_t)co0 * KD;
    const __half* b1base = g_x1T + (size_t)nimg*PPAD*CI;
    const __half* b2base = g_x2T + (size_t)nimg*PPAD*CI;

    // per-thread B-load geometry (one (row,ch) pair, both splits)
    int brow = tid >> 2;                // 0..63 (pixel row in tile)
    int bch8 = (tid & 3) * 8;           // half offset within 32-K chunk
    int pxT = px0 + brow;
    int yT = pxT / 76, xT = pxT - yT*76;

    // ldmatrix byte offsets (stride 40 halves, ks adds 32B)
    int l15 = lane & 15;
    int lAc = (lane >> 4) * 8;
    int l7  = lane & 7;
    int lBc = ((lane >> 3) & 1) * 8;
    int lBr = (lane >> 4) * 8;
    uint32_t aoff[2][2][2], boff[2][2][2];
#pragma unroll
    for (int sp = 0; sp < 2; ++sp)
#pragma unroll
        for (int mt = 0; mt < 2; ++mt)
#pragma unroll
            for (int ks = 0; ks < 2; ++ks)
                aoff[sp][mt][ks] = (uint32_t)((sp*A_SP + (wm + mt*16 + l15)*40 + ks*16 + lAc) * 2);
#pragma unroll
    for (int sp = 0; sp < 2; ++sp)
#pragma unroll
        for (int g = 0; g < 2; ++g)
#pragma unroll
            for (int ks = 0; ks < 2; ++ks)
                boff[sp][g][ks] = (uint32_t)((2*A_SP + sp*B_SP + (wn + g*16 + l7 + lBr)*40 + ks*16 + lBc) * 2);

#define LOAD_STAGE(it, s) do { \
    int k0 = (it) * KC; \
    int r_  = (it) >> 4; \
    int ci0_ = ((it) & 15) * 32; \
    int dy_ = r_/3 - 1; \
    int dx_ = r_ - (r_/3)*3 - 1; \
    int dd_ = dy_*76 + dx_; \
    bool vT = ((unsigned)(xT + dx_) < 76u) && ((unsigned)(yT + dy_) < 50u) && (pxT < P); \
    uint32_t szT = vT ? 16u : 0u; \
    _Pragma("unroll") \
    for (int i = 0; i < 4; ++i) { \
        int c = tid + i*256; \
        int split = c >> 9, rc = c & 511, row = rc >> 2, ch = rc & 3; \
        uint32_t dsth = (uint32_t)((s)*STAGE_H + split*A_SP + row*40 + ch*8); \
        const __half* src = (split ? w2b : w1b) + (size_t)row*KD + k0 + ch*8; \
        CP16(sbase + dsth*2, (const void*)src); \
    } \
    { \
        size_t oT = vT ? ((size_t)(pxT + dd_)*CI + ci0_ + bch8) : 0; \
        uint32_t dB = (uint32_t)((s)*STAGE_H + 2*A_SP + brow*40 + bch8); \
        CP16Z(sbase + dB*2,            (const void*)(b1base + oT), szT); \
        CP16Z(sbase + (dB + B_SP)*2,   (const void*)(b2base + oT), szT); \
    } \
    CP_COMMIT(); \
} while (0)

    LOAD_STAGE(0, 0);
    LOAD_STAGE(1, 1);

    for (int it = 0; it < NSTG; ++it) {
        int s = it % 3;
        CP_WAIT1();
        __syncthreads();
        if (it + 2 < NSTG) { int it2 = it + 2; LOAD_STAGE(it2, it2 % 3); }
        else               { CP_COMMIT(); }
        uint32_t stB = sbase + (uint32_t)(s * STAGE_H * 2);
#pragma unroll
        for (int ks = 0; ks < 2; ++ks) {
            uint32_t a1f[2][4], a2f[2][4], bt[4], b1f[4][2], b2f[4][2];
            LDSM4(a1f[0], stB + aoff[0][0][ks]);
            LDSM4(a1f[1], stB + aoff[0][1][ks]);
            LDSM4(a2f[0], stB + aoff[1][0][ks]);
            LDSM4(a2f[1], stB + aoff[1][1][ks]);
            LDSM4(bt, stB + boff[0][0][ks]);
            b1f[0][0]=bt[0]; b1f[0][1]=bt[1]; b1f[1][0]=bt[2]; b1f[1][1]=bt[3];
            LDSM4(bt, stB + boff[0][1][ks]);
            b1f[2][0]=bt[0]; b1f[2][1]=bt[1]; b1f[3][0]=bt[2]; b1f[3][1]=bt[3];
            LDSM4(bt, stB + boff[1][0][ks]);
            b2f[0][0]=bt[0]; b2f[0][1]=bt[1]; b2f[1][0]=bt[2]; b2f[1][1]=bt[3];
            LDSM4(bt, stB + boff[1][1][ks]);
            b2f[2][0]=bt[0]; b2f[2][1]=bt[1]; b2f[3][0]=bt[2]; b2f[3][1]=bt[3];
#pragma unroll
            for (int mt = 0; mt < 2; ++mt)
#pragma unroll
                for (int nt = 0; nt < 4; ++nt) {
                    MMA16816(acc1[mt][nt], a1f[mt], b1f[nt]);
                    MMA16816(acc2[mt][nt], a1f[mt], b2f[nt]);
                    MMA16816(acc2[mt][nt], a2f[mt], b1f[nt]);
                }
        }
    }

    __syncthreads();
    float* stg = (float*)sh;
    const float inv = 1.f / 4096.f;
#pragma unroll
    for (int mt = 0; mt < 2; ++mt)
#pragma unroll
        for (int nt = 0; nt < 4; ++nt) {
            int row = wm + mt * 16 + r0;
            int col = wn + nt * 8 + (lane & 3) * 2;
            stg[ row      * 66 + col    ] = acc1[mt][nt][0] + acc2[mt][nt][0] * inv;
            stg[ row      * 66 + col + 1] = acc1[mt][nt][1] + acc2[mt][nt][1] * inv;
            stg[(row + 8) * 66 + col    ] = acc1[mt][nt][2] + acc2[mt][nt][2] * inv;
            stg[(row + 8) * 66 + col + 1] = acc1[mt][nt][3] + acc2[mt][nt][3] * inv;
        }
    __syncthreads();
    for (int e = tid; e < 128 * 64; e += 256) {
        int row = e >> 6, col = e & 63;
        int px = px0 + col;
        if (px < P) {
            float v = stg[row * 66 + col] + bias[co0 + row];
            g_feat[((size_t)nimg * CO + co0 + row) * P + px] = fmaxf(v, 0.f);
        }
    }
}

// ---------------- fused heads + softmax + loc2bbox/clip/minsize/keys ----------------
__device__ __forceinline__ float read_dim(const void* p)
{
    int v = *(const int*)p;
    if (v > 0 && v < 100000) return (float)v;
    return __int_as_float(v);
}

// 4 threads per pixel: thread q accumulates ci in [q*128, q*128+128), quad shuffle-reduce.
__global__ __launch_bounds__(256) void heads_prep_kernel(const float* __restrict__ sw,
                                                         const float* __restrict__ sbias,
                                                         const float* __restrict__ lw,
                                                         const float* __restrict__ lb,
                                                         float* __restrict__ out,
                                                         const void* __restrict__ ihp,
                                                         const void* __restrict__ iwp)
{
    extern __shared__ float ws[];   // [512][54]
    int n = blockIdx.y;
    int tid = threadIdx.x;
    int p = blockIdx.x * 64 + (tid >> 2);
    int q = tid & 3;

    for (int e = tid; e < 512*54; e += 256) {
        int ci = e / 54, ch = e - ci*54;
        ws[e] = (ch < 18) ? sw[ch*512 + ci] : lw[(ch-18)*512 + ci];
    }
    __syncthreads();

    float acc[54];
#pragma unroll
    for (int c = 0; c < 54; ++c) acc[c] = 0.f;

    int pc = p < P ? p : P - 1;
    const float* f = g_feat + (size_t)n*CO*P + pc;
    int ci_beg = q * 128;
    for (int ci = ci_beg; ci < ci_beg + 128; ci += 4) {
        float fv0 = f[(size_t)(ci  )*P];
        float fv1 = f[(size_t)(ci+1)*P];
        float fv2 = f[(size_t)(ci+2)*P];
        float fv3 = f[(size_t)(ci+3)*P];
        const float* w0 = ws + (ci  )*54;
        const float* w1 = ws + (ci+1)*54;
        const float* w2 = ws + (ci+2)*54;
        const float* w3 = ws + (ci+3)*54;
#pragma unroll
        for (int ch = 0; ch < 54; ++ch) {
            float a = acc[ch];
            a = fmaf(fv0, w0[ch], a);
            a = fmaf(fv1, w1[ch], a);
            a = fmaf(fv2, w2[ch], a);
            a = fmaf(fv3, w3[ch], a);
            acc[ch] = a;
        }
    }

    // quad reduce: lanes (4k..4k+3) hold partials for the same pixel
#pragma unroll
    for (int ch = 0; ch < 54; ++ch) {
        float a = acc[ch];
        a += __shfl_xor_sync(0xffffffffu, a, 1);
        a += __shfl_xor_sync(0xffffffffu, a, 2);
        acc[ch] = a;
    }

    if (q == 0 && p < P) {
        float* locs   = out + OFF_LOCS;
        float* scores = out + OFF_SCORES;
        float IW = read_dim(iwp), IH = read_dim(ihp);
        int yy = p / FW, xx = p - yy*FW;
        float sxp = xx * 16.f, syp = yy * 16.f;
        const float ratios[3] = {0.5f, 1.f, 2.f};
        const float scales[3] = {8.f, 16.f, 32.f};
#pragma unroll
        for (int a = 0; a < 9; ++a) {
            float s0 = acc[a*2]   + sbias[a*2];
            float s1 = acc[a*2+1] + sbias[a*2+1];
            int i = n*NA + p*9 + a;
            scores[(size_t)i*2]   = s0;
            scores[(size_t)i*2+1] = s1;
            float m  = fmaxf(s0, s1);
            float e0 = expf(s0 - m), e1 = expf(s1 - m);
            float fg = e1 / (e0 + e1);
            float l0 = acc[18 + a*4 + 0] + lb[a*4 + 0];
            float l1 = acc[18 + a*4 + 1] + lb[a*4 + 1];
            float l2 = acc[18 + a*4 + 2] + lb[a*4 + 2];
            float l3 = acc[18 + a*4 + 3] + lb[a*4 + 3];
            locs[(size_t)i*4 + 0] = l0;
            locs[(size_t)i*4 + 1] = l1;
            locs[(size_t)i*4 + 2] = l2;
            locs[(size_t)i*4 + 3] = l3;
            float r  = ratios[a/3];
            float sc = scales[a%3];
            float hh = 16.f * sc * sqrtf(r);
            float ww = 16.f * sc * sqrtf(1.f/r);
            float a0 = sxp + 8.f - ww*0.5f;
            float a1 = syp + 8.f - hh*0.5f;
            float a2 = sxp + 8.f + ww*0.5f;
            float a3 = syp + 8.f + hh*0.5f;
            float aw = a2 - a0, ah = a3 - a1;
            float ax = a0 + 0.5f*aw, ay = a1 + 0.5f*ah;
            float cx = l0*aw + ax;
            float cy = l1*ah + ay;
            float wb = expf(l2)*aw;
            float hb = expf(l3)*ah;
            float x1 = fminf(fmaxf(cx - 0.5f*wb, 0.f), IW);
            float y1 = fminf(fmaxf(cy - 0.5f*hb, 0.f), IH);
            float x2 = fminf(fmaxf(cx + 0.5f*wb, 0.f), IW);
            float y2 = fminf(fmaxf(cy + 0.5f*hb, 0.f), IH);
            float* rr = g_roi + ((size_t)n*NA + (size_t)(p*9 + a))*4;
            rr[0] = x1; rr[1] = y1; rr[2] = x2; rr[3] = y2;
            bool valid = ((x2 - x1) >= 16.f) && ((y2 - y1) >= 16.f);
            g_key[(size_t)n*NSORT + p*9 + a] = valid ? fg : -INFINITY;
        }
    }
}

// ---------------- histogram select + single-block exact top sort ----------------
__device__ __forceinline__ bool sbefore(float ka, int ia, float kb, int ib)
{
    if (ka > kb) return true;
    if (ka < kb) return false;
    return ia < ib;
}

__device__ __forceinline__ void suffix_scan_1024(unsigned* tpart, int t)
{
    for (int off = 1; off < 1024; off <<= 1) {
        unsigned v = tpart[t] + ((t + off < 1024) ? tpart[t + off] : 0u);
        __syncthreads();
        tpart[t] = v;
        __syncthreads();
    }
}

#define SMEM_SEL (32768 + 32768 + 16384 + 4096)

__global__ __launch_bounds__(1024) void select_sort_kernel(void)
{
    extern __shared__ char smem[];
    float*    skey = (float*)smem;
    int*      sidx = (int*)(smem + 32768);
    unsigned* hist = (unsigned*)(smem + 65536);
    unsigned* tpart = (unsigned*)(smem + 81920);
    __shared__ unsigned sB1, sHi1, sCnt1, sTotal, sB2;
    __shared__ int sCnt;

    int n = blockIdx.x;
    int t = threadIdx.x;
    const float* keys = g_key + (size_t)n * NSORT;

    for (int b = t; b < 4096; b += 1024) hist[b] = 0u;
    if (t == 0) { sCnt = 0; sB1 = 0u; sHi1 = 0u; sCnt1 = 0u; sB2 = 0u; }
    __syncthreads();
    for (int i = t; i < NA; i += 1024) {
        unsigned u = __float_as_uint(keys[i]);
        if (!(u >> 31)) atomicAdd(&hist[u >> 20], 1u);
    }
    __syncthreads();
    { int b0 = t*4; tpart[t] = hist[b0] + hist[b0+1] + hist[b0+2] + hist[b0+3]; }
    __syncthreads();
    suffix_scan_1024(tpart, t);
    {
        unsigned beyond = (t < 1023) ? tpart[t+1] : 0u;
        int b0 = t * 4;
        unsigned h3 = hist[b0+3], h2 = hist[b0+2], h1 = hist[b0+1], h0 = hist[b0];
        unsigned hi3 = beyond, hi2 = beyond + h3, hi1v = hi2 + h2, hi0 = hi1v + h1;
        if (hi0  < PRE && PRE <= hi0  + h0) { sB1 = b0;   sHi1 = hi0;  sCnt1 = h0; }
        if (hi1v < PRE && PRE <= hi1v + h1) { sB1 = b0+1; sHi1 = hi1v; sCnt1 = h1; }
        if (hi2  < PRE && PRE <= hi2  + h2) { sB1 = b0+2; sHi1 = hi2;  sCnt1 = h2; }
        if (hi3  < PRE && PRE <= hi3  + h3) { sB1 = b0+3; sHi1 = hi3;  sCnt1 = h3; }
        if (t == 0) sTotal = tpart[0];
    }
    __syncthreads();

    unsigned TB;
    if (sTotal <= (unsigned)NSEL) {
        TB = 0u;
    } else if (sHi1 + sCnt1 <= (unsigned)NSEL) {
        TB = sB1 << 12;
    } else {
        unsigned B1 = sB1, R = (unsigned)PRE - sHi1;
        __syncthreads();
        for (int b = t; b < 4096; b += 1024) hist[b] = 0u;
        __syncthreads();
        for (int i = t; i < NA; i += 1024) {
            unsigned u = __float_as_uint(keys[i]);
            if (!(u >> 31) && (u >> 20) == B1) atomicAdd(&hist[(u >> 8) & 0xFFFu], 1u);
        }
        __syncthreads();
        { int b0 = t*4; tpart[t] = hist[b0] + hist[b0+1] + hist[b0+2] + hist[b0+3]; }
        __syncthreads();
        suffix_scan_1024(tpart, t);
        {
            unsigned beyond = (t < 1023) ? tpart[t+1] : 0u;
            int b0 = t * 4;
            unsigned h3 = hist[b0+3], h2 = hist[b0+2], h1 = hist[b0+1], h0 = hist[b0];
            unsigned hi3 = beyond, hi2 = beyond + h3, hi1v = hi2 + h2, hi0 = hi1v + h1;
            if (hi0  < R && R <= hi0  + h0) sB2 = b0;
            if (hi1v < R && R <= hi1v + h1) sB2 = b0+1;
            if (hi2  < R && R <= hi2  + h2) sB2 = b0+2;
            if (hi3  < R && R <= hi3  + h3) sB2 = b0+3;
        }
        __syncthreads();
        TB = (B1 << 12) | sB2;
    }
    __syncthreads();

    for (int i = t; i < NA; i += 1024) {
        float k = keys[i];
        unsigned u = __float_as_uint(k);
        if (!(u >> 31) && (u >> 8) >= TB) {
            int pos = atomicAdd(&sCnt, 1);
            if (pos < NSEL) { skey[pos] = k; sidx[pos] = i; }
        }
    }
    __syncthreads();
    int cnt = sCnt < NSEL ? sCnt : NSEL;
    for (int i = cnt + t; i < NSEL; i += 1024) { skey[i] = -INFINITY; sidx[i] = 0x7FFFFFFF; }
    __syncthreads();

    for (int k = 2; k <= NSEL; k <<= 1) {
        for (int j = k >> 1; j >= 1; j >>= 1) {
#pragma unroll
            for (int l = 0; l < 4; ++l) {
                int e = t + l * 1024;
                int i1 = ((e & ~(j-1)) << 1) | (e & (j-1));
                int i2 = i1 + j;
                bool up = ((i1 & k) == 0);
                float ka = skey[i1], kb = skey[i2];
                int ia = sidx[i1], ib = sidx[i2];
                if (sbefore(ka, ia, kb, ib) != up) {
                    skey[i1] = kb; sidx[i1] = ib; skey[i2] = ka; sidx[i2] = ia;
                }
            }
            __syncthreads();
        }
    }

    for (int i = t; i < NSEL; i += 1024) {
        g_key[(size_t)n*NSORT + i] = skey[i];
        g_idx[(size_t)n*NSORT + i] = sidx[i];
    }
}

// ---------------- greedy NMS (exact, two-level chunked) + top-300 ----------------
__device__ __forceinline__ bool iou_gt(float ax1, float ay1, float ax2, float ay2, float aa,
                                       float bx1, float by1, float bx2, float by2, float ba)
{
    float ix1 = fmaxf(ax1, bx1);
    float iy1 = fmaxf(ay1, by1);
    float ix2 = fminf(ax2, bx2);
    float iy2 = fminf(ay2, by2);
    float inter = fmaxf(ix2 - ix1, 0.f) * fmaxf(iy2 - iy1, 0.f);
    float iou = inter / (aa + ba - inter + 1e-9f);
    return iou > 0.7f;
}

__global__ __launch_bounds__(1024) void nms_kernel(float* __restrict__ out)
{
    extern __shared__ float sm[];
    float* x1 = sm;
    float* y1 = sm + PRE;
    float* x2 = sm + 2*PRE;
    float* y2 = sm + 3*PRE;
    float* ar = sm + 4*PRE;
    unsigned char* keep = (unsigned char*)(sm + 5*PRE);
    __shared__ unsigned long long msk[64];
    __shared__ int kidx[64];
    __shared__ int kcnt;
    __shared__ int wsum[32];

    int n = blockIdx.x;
    int t = threadIdx.x;

    for (int i = t; i < PRE; i += 1024) {
        float k = g_key[(size_t)n*NSORT + i];
        if (isfinite(k)) {
            int id = g_idx[(size_t)n*NSORT + i];
            const float* r = g_roi + ((size_t)n*NA + id)*4;
            x1[i] = r[0]; y1[i] = r[1]; x2[i] = r[2]; y2[i] = r[3];
            ar[i] = (r[2]-r[0])*(r[3]-r[1]);
            keep[i] = 1;
        } else {
            x1[i] = y1[i] = x2[i] = y2[i] = ar[i] = 0.f;
            keep[i] = 0;
        }
    }
    for (int e = t; e < POST*4; e += 1024)
        out[OFF_ROIS + n*POST*4 + e] = 0.f;
    __syncthreads();

    for (int c0 = 0; c0 < PRE; c0 += 64) {
        int cend = c0 + 64 < PRE ? c0 + 64 : PRE;
        int cn = cend - c0;

        if (t < 64) {
            unsigned long long m = 0ull;
            if (t < cn && keep[c0 + t]) {
                float bx1 = x1[c0+t], by1 = y1[c0+t], bx2 = x2[c0+t], by2 = y2[c0+t], ba = ar[c0+t];
                for (int k = t + 1; k < cn; ++k) {
                    if (iou_gt(bx1, by1, bx2, by2, ba,
                               x1[c0+k], y1[c0+k], x2[c0+k], y2[c0+k], ar[c0+k]))
                        m |= 1ull << k;
                }
            }
            msk[t] = m;
        }
        __syncthreads();

        if (t < 32) {
            unsigned long long m0 = msk[t], m1 = msk[t + 32];
            unsigned b0 = __ballot_sync(0xffffffffu, (t < cn) && keep[c0 + t]);
            unsigned b1 = __ballot_sync(0xffffffffu, (t + 32 < cn) && keep[c0 + t + 32]);
            unsigned long long kmask = (unsigned long long)b0 | ((unsigned long long)b1 << 32);
            unsigned long long rm = 0ull, fk = 0ull;
            for (int k = 0; k < cn; ++k) {
                bool kp = ((kmask >> k) & 1ull) && !((rm >> k) & 1ull);
                if (kp) {
                    fk |= 1ull << k;
                    unsigned long long src = (k < 32) ? m0 : m1;
                    unsigned lo = __shfl_sync(0xffffffffu, (unsigned)src, k & 31);
                    unsigned hi = __shfl_sync(0xffffffffu, (unsigned)(src >> 32), k & 31);
                    rm |= ((unsigned long long)hi << 32) | lo;
                }
            }
            if (t < cn) {
                bool kp = (fk >> t) & 1ull;
                keep[c0 + t] = kp;
                if (kp) kidx[__popcll(fk & ((1ull << t) - 1ull))] = c0 + t;
            }
            if (t + 32 < cn) {
                bool kp = (fk >> (t + 32)) & 1ull;
                keep[c0 + t + 32] = kp;
                if (kp) kidx[__popcll(fk & ((1ull << (t + 32)) - 1ull))] = c0 + t + 32;
            }
            if (t == 0) kcnt = (int)__popcll(fk);
        }
        __syncthreads();

        int kc = kcnt;
        if (kc > 0) {
            for (int j = cend + t; j < PRE; j += 1024) {
                if (keep[j]) {
                    float jx1 = x1[j], jy1 = y1[j], jx2 = x2[j], jy2 = y2[j], ja = ar[j];
                    for (int q = 0; q < kc; ++q) {
                        int i = kidx[q];
                        if (iou_gt(x1[i], y1[i], x2[i], y2[i], ar[i],
                                   jx1, jy1, jx2, jy2, ja)) { keep[j] = 0; break; }
                    }
                }
            }
        }
        __syncthreads();
    }

    int base_i = t * 6;
    int loc[6];
    int lsum = 0;
#pragma unroll
    for (int q = 0; q < 6; ++q) {
        int ii = base_i + q;
        int v = (ii < PRE) ? (int)keep[ii] : 0;
        loc[q] = lsum;
        lsum += v;
    }
    int lane = t & 31, wid = t >> 5;
    int v = lsum;
    for (int o = 1; o < 32; o <<= 1) {
        int u = __shfl_up_sync(0xffffffffu, v, o);
        if (lane >= o) v += u;
    }
    if (lane == 31) wsum[wid] = v;
    __syncthreads();
    if (wid == 0) {
        int w2 = wsum[lane];
        for (int o = 1; o < 32; o <<= 1) {
            int u = __shfl_up_sync(0xffffffffu, w2, o);
            if (lane >= o) w2 += u;
        }
        wsum[lane] = w2;
    }
    __syncthreads();
    int excl = v - lsum + (wid > 0 ? wsum[wid-1] : 0);
#pragma unroll
    for (int q = 0; q < 6; ++q) {
        int ii = base_i + q;
        if (ii < PRE && keep[ii]) {
            int r = excl + loc[q];
            if (r < POST) {
                float* o = out + OFF_ROIS + ((size_t)n*POST + r)*4;
                o[0] = x1[ii]; o[1] = y1[ii]; o[2] = x2[ii]; o[3] = y2[ii];
            }
        }
    }
}

// ---------------- launch ----------------
extern "C" void kernel_launch(void* const* d_in, const int* in_sizes, int n_in,
                              void* d_out, int out_size)
{
    const float* x   = (const float*)d_in[0];
    const float* w1  = (const float*)d_in[1];
    const float* bc  = (const float*)d_in[2];
    const float* sw  = (const float*)d_in[3];
    const float* sbb = (const float*)d_in[4];
    const float* lw  = (const float*)d_in[5];
    const float* lb  = (const float*)d_in[6];
    const void*  ih  = d_in[7];
    const void*  iw  = d_in[8];
    float* out = (float*)d_out;

    static bool attr_done = false;
    if (!attr_done) {
        cudaFuncSetAttribute(conv_mma_kernel, cudaFuncAttributeMaxDynamicSharedMemorySize, SMEM_CONV);
        cudaFuncSetAttribute(heads_prep_kernel, cudaFuncAttributeMaxDynamicSharedMemorySize, 512*54*4);
        cudaFuncSetAttribute(select_sort_kernel, cudaFuncAttributeMaxDynamicSharedMemorySize, SMEM_SEL);
        cudaFuncSetAttribute(nms_kernel, cudaFuncAttributeMaxDynamicSharedMemorySize, 131072);
        attr_done = true;
    }

    fuse1_kernel<<<(N_FUSE1 + 255)/256, 256>>>(w1, out);
    xpose_kernel<<<dim3(60, 16, BATCH), 256>>>(x);
    conv_mma_kernel<<<dim3(CO/128, PPAD/64, BATCH), 256, SMEM_CONV>>>(bc);
    heads_prep_kernel<<<dim3((P + 63)/64, BATCH), 256, 512*54*4>>>(sw, sbb, lw, lb, out, ih, iw);
    select_sort_kernel<<<BATCH, 1024, SMEM_SEL>>>();
    nms_kernel<<<BATCH, 1024, 5*PRE*4 + PRE>>>(out);
}

// round 16
// speedup vs baseline: 2.7669x; 2.7669x over previous
#include <cuda_runtime.h>
#include <cuda_fp16.h>
#include <math.h>
#include <stdint.h>

#define BATCH 8
#define CI 512
#define CO 512
#define FH 50
#define FW 76
#define P 3800           // FH*FW
#define PPAD 3840        // padded pixels per image
#define NA 34200         // P*9
#define KD 4608          // 9*CI  (K order: r*512 + ci)
#define NSORT 65536
#define PRE 6000
#define POST 300
#define NSEL 8192
#define NROW 6016        // 94*64
#define NW 94            // mask words per row

#define OFF_LOCS   0
#define OFF_SCORES 1094400
#define OFF_ROIS   1641600
#define OFF_ANCH   1651200

// ---------------- device scratch ----------------
__device__ float g_feat[BATCH*CO*P];
__device__ float g_roi[BATCH*NA*4];
__device__ float g_key[BATCH*NSORT];

__device__ __align__(16) __half g_w1h[CO*KD];
__device__ __align__(16) __half g_w2h[CO*KD];
__device__ __align__(16) __half g_x1T[(size_t)BATCH*PPAD*CI];
__device__ __align__(16) __half g_x2T[(size_t)BATCH*PPAD*CI];

// sorted-box arrays (filled by select_sort)
__device__ float g_sx1[BATCH*NROW];
__device__ float g_sy1[BATCH*NROW];
__device__ float g_sx2[BATCH*NROW];
__device__ float g_sy2[BATCH*NROW];
__device__ float g_sar[BATCH*NROW];
__device__ unsigned long long g_validw[BATCH*NW];
__device__ unsigned long long g_mask[(size_t)BATCH*NROW*NW];

// ---------------- helpers ----------------
__device__ __forceinline__ uint32_t smem_u32(const void* p){
    uint32_t a;
    asm("{ .reg .u64 t; cvta.to.shared.u64 t, %1; cvt.u32.u64 %0, t; }" : "=r"(a) : "l"(p));
    return a;
}
#define CP16(dst, src)       asm volatile("cp.async.cg.shared.global [%0], [%1], 16;" :: "r"(dst), "l"(src))
#define CP16Z(dst, src, sz)  asm volatile("cp.async.cg.shared.global [%0], [%1], 16, %2;" :: "r"(dst), "l"(src), "r"(sz))
#define CP_COMMIT()          asm volatile("cp.async.commit_group;" ::: "memory")
#define CP_WAIT1()           asm volatile("cp.async.wait_group 1;" ::: "memory")

#define MMA16816(d, a, b) asm volatile( \
    "mma.sync.aligned.m16n8k16.row.col.f32.f16.f16.f32 " \
    "{%0,%1,%2,%3}, {%4,%5,%6,%7}, {%8,%9}, {%0,%1,%2,%3};" \
    : "+f"((d)[0]), "+f"((d)[1]), "+f"((d)[2]), "+f"((d)[3]) \
    : "r"((a)[0]), "r"((a)[1]), "r"((a)[2]), "r"((a)[3]), \
      "r"((b)[0]), "r"((b)[1]))

#define LDSM4(r, a) asm volatile( \
    "ldmatrix.sync.aligned.m8n8.x4.shared.b16 {%0,%1,%2,%3}, [%4];" \
    : "=r"((r)[0]), "=r"((r)[1]), "=r"((r)[2]), "=r"((r)[3]) : "r"(a))

// ---------------- fused: weight split+reorder + anchors ----------------
#define N_WCVT (CO*KD)
#define N_ANCH NA
#define N_FUSE1 (N_WCVT + N_ANCH)

__global__ void fuse1_kernel(const float* __restrict__ w, float* __restrict__ out)
{
    int t = blockIdx.x*256 + threadIdx.x;
    if (t < N_WCVT) {
        int co = t / KD;
        int k  = t - co*KD;
        int r  = k >> 9;
        int ci = k & 511;
        float v = w[co*KD + ci*9 + r];
        __half h1 = __float2half_rn(v);
        float rr = v - __half2float(h1);
        __half h2 = __float2half_rn(rr * 4096.f);
        g_w1h[t] = h1; g_w2h[t] = h2;
        return;
    }
    int t2 = t - N_WCVT;
    if (t2 < N_ANCH) {
        int i = t2;
        int p = i / 9, a = i - p*9;
        int y = p / FW, x = p - y*FW;
        const float ratios[3] = {0.5f, 1.f, 2.f};
        const float scales[3] = {8.f, 16.f, 32.f};
        float r  = ratios[a/3];
        float sc = scales[a%3];
        float hh = 16.f * sc * sqrtf(r);
        float ww = 16.f * sc * sqrtf(1.f/r);
        float sx = x * 16.f, sy = y * 16.f;
        float* o = out + OFF_ANCH + (size_t)i*4;
        o[0] = sx + 8.f - ww*0.5f; o[1] = sy + 8.f - hh*0.5f;
        o[2] = sx + 8.f + ww*0.5f; o[3] = sy + 8.f + hh*0.5f;
    }
}

// ---------------- transpose x -> channel-last fp16 hi/lo ----------------
__global__ __launch_bounds__(256) void xpose_kernel(const float* __restrict__ x)
{
    __shared__ float sx[32][65];
    int px0 = blockIdx.x * 64;
    int ci0 = blockIdx.y * 32;
    int n   = blockIdx.z;
    int tid = threadIdx.x;

#pragma unroll
    for (int l = 0; l < 8; ++l) {
        int idx = tid + l*256;
        int row = idx >> 6, col = idx & 63;
        int gp = px0 + col;
        sx[row][col] = (gp < P) ? x[((size_t)n*CI + ci0 + row)*P + gp] : 0.f;
    }
    __syncthreads();

    int px_l = tid >> 2;
    int g    = tid & 3;
    float v[8];
#pragma unroll
    for (int q = 0; q < 8; ++q) v[q] = sx[g*8 + q][px_l];

    __half2 h1[4], h2[4];
#pragma unroll
    for (int j = 0; j < 4; ++j) {
        h1[j] = __floats2half2_rn(v[2*j], v[2*j+1]);
        float r0 = (v[2*j]   - __low2float(h1[j]))  * 4096.f;
        float r1 = (v[2*j+1] - __high2float(h1[j])) * 4096.f;
        h2[j] = __floats2half2_rn(r0, r1);
    }
    size_t o = ((size_t)n*PPAD + px0 + px_l)*CI + ci0 + g*8;
    *(uint4*)(g_x1T + o) = *(const uint4*)h1;
    *(uint4*)(g_x2T + o) = *(const uint4*)h2;
}

// ---------------- conv1: implicit im2col, KC=64, 2-stage (R13 config) ----------------
#define KC 64
#define NSTG 72
#define A_SP 9216
#define B_SP 4608
#define STAGE_H 27648
#define SMEM_CONV (2*STAGE_H*2)

__global__ __launch_bounds__(256, 2) void conv_mma_kernel(const float* __restrict__ bias)
{
    extern __shared__ __half sh[];
    uint32_t sbase = smem_u32(sh);

    int tid  = threadIdx.x;
    int wid  = tid >> 5;
    int lane = tid & 31;
    int nimg = blockIdx.z;
    int co0  = blockIdx.x * 128;
    int px0  = blockIdx.y * 64;

    int wm = (wid & 3) * 32;
    int wn = (wid >> 2) * 32;
    int r0 = lane >> 2;

    float acc1[2][4][4], acc2[2][4][4];
#pragma unroll
    for (int mt = 0; mt < 2; ++mt)
#pragma unroll
        for (int nt = 0; nt < 4; ++nt)
#pragma unroll
            for (int c = 0; c < 4; ++c) { acc1[mt][nt][c] = 0.f; acc2[mt][nt][c] = 0.f; }

    const __half* w1b = g_w1h + (size_t)co0 * KD;
    const __half* w2b = g_w2h + (size_t)co0 * KD;
    const __half* b1base = g_x1T + (size_t)nimg*PPAD*CI;
    const __half* b2base = g_x2T + (size_t)nimg*PPAD*CI;

    int ch8   = (tid & 7) * 8;
    int brow0 = tid >> 3;
    int pxA = px0 + brow0;
    int pxB = px0 + brow0 + 32;
    int yA = pxA / 76, xA = pxA - yA*76;
    int yB = pxB / 76, xB = pxB - yB*76;

    int l15 = lane & 15;
    int lAc = (lane >> 4) * 8;
    int l7  = lane & 7;
    int lBc = ((lane >> 3) & 1) * 8;
    int lBr = (lane >> 4) * 8;
    uint32_t aoff[2][2], boff[2][2];
#pragma unroll
    for (int sp = 0; sp < 2; ++sp)
#pragma unroll
        for (int mt = 0; mt < 2; ++mt)
            aoff[sp][mt] = (uint32_t)((sp*A_SP + (wm + mt*16 + l15)*72 + lAc) * 2);
#pragma unroll
    for (int sp = 0; sp < 2; ++sp)
#pragma unroll
        for (int g = 0; g < 2; ++g)
            boff[sp][g] = (uint32_t)((2*A_SP + sp*B_SP + (wn + g*16 + l7 + lBr)*72 + lBc) * 2);

#define LOAD_STAGE(it, s) do { \
    int k0 = (it) * KC; \
    int r_  = (it) >> 3; \
    int ci0_ = ((it) & 7) * 64; \
    int dy_ = r_/3 - 1; \
    int dx_ = r_ - (r_/3)*3 - 1; \
    int dd_ = dy_*76 + dx_; \
    bool vA = ((unsigned)(xA + dx_) < 76u) && ((unsigned)(yA + dy_) < 50u) && (pxA < P); \
    bool vB = ((unsigned)(xB + dx_) < 76u) && ((unsigned)(yB + dy_) < 50u) && (pxB < P); \
    uint32_t szA = vA ? 16u : 0u, szB = vB ? 16u : 0u; \
    _Pragma("unroll") \
    for (int i = 0; i < 8; ++i) { \
        int c = tid + i*256; \
        int split = c >> 10, rc = c & 1023, row = rc >> 3, ch = rc & 7; \
        uint32_t dsth = (uint32_t)((s)*STAGE_H + split*A_SP + row*72 + ch*8); \
        const __half* src = (split ? w2b : w1b) + (size_t)row*KD + k0 + ch*8; \
        CP16(sbase + dsth*2, (const void*)src); \
    } \
    { \
        size_t oA = vA ? ((size_t)(pxA + dd_)*CI + ci0_ + ch8) : 0; \
        size_t oB = vB ? ((size_t)(pxB + dd_)*CI + ci0_ + ch8) : 0; \
        uint32_t dB = (uint32_t)((s)*STAGE_H + 2*A_SP); \
        CP16Z(sbase + (dB +        brow0      *72 + ch8)*2, (const void*)(b1base + oA), szA); \
        CP16Z(sbase + (dB +       (brow0+32) *72 + ch8)*2, (const void*)(b1base + oB), szB); \
        CP16Z(sbase + (dB + B_SP + brow0      *72 + ch8)*2, (const void*)(b2base + oA), szA); \
        CP16Z(sbase + (dB + B_SP + (brow0+32)*72 + ch8)*2, (const void*)(b2base + oB), szB); \
    } \
    CP_COMMIT(); \
} while (0)

    LOAD_STAGE(0, 0);
    LOAD_STAGE(1, 1);

    for (int it = 0; it < NSTG; ++it) {
        int s = it & 1;
        CP_WAIT1();
        __syncthreads();
        uint32_t stB = sbase + (uint32_t)(s * STAGE_H * 2);
#pragma unroll
        for (int ks = 0; ks < 4; ++ks) {
            uint32_t ko = (uint32_t)(ks * 32);
            uint32_t a1f[2][4], a2f[2][4], bt[4], b1f[4][2], b2f[4][2];
            LDSM4(a1f[0], stB + aoff[0][0] + ko);
            LDSM4(a1f[1], stB + aoff[0][1] + ko);
            LDSM4(a2f[0], stB + aoff[1][0] + ko);
            LDSM4(a2f[1], stB + aoff[1][1] + ko);
            LDSM4(bt, stB + boff[0][0] + ko);
            b1f[0][0]=bt[0]; b1f[0][1]=bt[1]; b1f[1][0]=bt[2]; b1f[1][1]=bt[3];
            LDSM4(bt, stB + boff[0][1] + ko);
            b1f[2][0]=bt[0]; b1f[2][1]=bt[1]; b1f[3][0]=bt[2]; b1f[3][1]=bt[3];
            LDSM4(bt, stB + boff[1][0] + ko);
            b2f[0][0]=bt[0]; b2f[0][1]=bt[1]; b2f[1][0]=bt[2]; b2f[1][1]=bt[3];
            LDSM4(bt, stB + boff[1][1] + ko);
            b2f[2][0]=bt[0]; b2f[2][1]=bt[1]; b2f[3][0]=bt[2]; b2f[3][1]=bt[3];
#pragma unroll
            for (int mt = 0; mt < 2; ++mt)
#pragma unroll
                for (int nt = 0; nt < 4; ++nt) {
                    MMA16816(acc1[mt][nt], a1f[mt], b1f[nt]);
                    MMA16816(acc2[mt][nt], a1f[mt], b2f[nt]);
                    MMA16816(acc2[mt][nt], a2f[mt], b1f[nt]);
                }
        }
        __syncthreads();
        if (it + 2 < NSTG) { LOAD_STAGE(it + 2, s); }
        else               { CP_COMMIT(); }
    }

    __syncthreads();
    float* stg = (float*)sh;
    const float inv = 1.f / 4096.f;
#pragma unroll
    for (int mt = 0; mt < 2; ++mt)
#pragma unroll
        for (int nt = 0; nt < 4; ++nt) {
            int row = wm + mt * 16 + r0;
            int col = wn + nt * 8 + (lane & 3) * 2;
            stg[ row      * 66 + col    ] = acc1[mt][nt][0] + acc2[mt][nt][0] * inv;
            stg[ row      * 66 + col + 1] = acc1[mt][nt][1] + acc2[mt][nt][1] * inv;
            stg[(row + 8) * 66 + col    ] = acc1[mt][nt][2] + acc2[mt][nt][2] * inv;
            stg[(row + 8) * 66 + col + 1] = acc1[mt][nt][3] + acc2[mt][nt][3] * inv;
        }
    __syncthreads();
    for (int e = tid; e < 128 * 64; e += 256) {
        int row = e >> 6, col = e & 63;
        int px = px0 + col;
        if (px < P) {
            float v = stg[row * 66 + col] + bias[co0 + row];
            g_feat[((size_t)nimg * CO + co0 + row) * P + px] = fmaxf(v, 0.f);
        }
    }
}

// ---------------- fused heads + softmax + loc2bbox/clip/minsize/keys (R13) ----------------
__device__ __forceinline__ float read_dim(const void* p)
{
    int v = *(const int*)p;
    if (v > 0 && v < 100000) return (float)v;
    return __int_as_float(v);
}

__global__ __launch_bounds__(256) void heads_prep_kernel(const float* __restrict__ sw,
                                                         const float* __restrict__ sbias,
                                                         const float* __restrict__ lw,
                                                         const float* __restrict__ lb,
                                                         float* __restrict__ out,
                                                         const void* __restrict__ ihp,
                                                         const void* __restrict__ iwp)
{
    extern __shared__ float ws[];
    int n = blockIdx.y;
    int p = blockIdx.x * 256 + threadIdx.x;

    for (int e = threadIdx.x; e < 512*54; e += 256) {
        int ci = e / 54, ch = e - ci*54;
        ws[e] = (ch < 18) ? sw[ch*512 + ci] : lw[(ch-18)*512 + ci];
    }
    __syncthreads();

    float acc[54];
#pragma unroll
    for (int c = 0; c < 54; ++c) acc[c] = 0.f;

    int pc = p < P ? p : P - 1;
    const float* f = g_feat + (size_t)n*CO*P + pc;
    for (int ci = 0; ci < 512; ci += 4) {
        float fv0 = f[(size_t)(ci  )*P];
        float fv1 = f[(size_t)(ci+1)*P];
        float fv2 = f[(size_t)(ci+2)*P];
        float fv3 = f[(size_t)(ci+3)*P];
        const float* w0 = ws + (ci  )*54;
        const float* w1 = ws + (ci+1)*54;
        const float* w2 = ws + (ci+2)*54;
        const float* w3 = ws + (ci+3)*54;
#pragma unroll
        for (int ch = 0; ch < 54; ++ch) {
            float a = acc[ch];
            a = fmaf(fv0, w0[ch], a);
            a = fmaf(fv1, w1[ch], a);
            a = fmaf(fv2, w2[ch], a);
            a = fmaf(fv3, w3[ch], a);
            acc[ch] = a;
        }
    }

    if (p < P) {
        float* locs   = out + OFF_LOCS;
        float* scores = out + OFF_SCORES;
        float IW = read_dim(iwp), IH = read_dim(ihp);
        int yy = p / FW, xx = p - yy*FW;
        float sxp = xx * 16.f, syp = yy * 16.f;
        const float ratios[3] = {0.5f, 1.f, 2.f};
        const float scales[3] = {8.f, 16.f, 32.f};
#pragma unroll
        for (int a = 0; a < 9; ++a) {
            float s0 = acc[a*2]   + sbias[a*2];
            float s1 = acc[a*2+1] + sbias[a*2+1];
            int i = n*NA + p*9 + a;
            scores[(size_t)i*2]   = s0;
            scores[(size_t)i*2+1] = s1;
            float m  = fmaxf(s0, s1);
            float e0 = expf(s0 - m), e1 = expf(s1 - m);
            float fg = e1 / (e0 + e1);
            float l0 = acc[18 + a*4 + 0] + lb[a*4 + 0];
            float l1 = acc[18 + a*4 + 1] + lb[a*4 + 1];
            float l2 = acc[18 + a*4 + 2] + lb[a*4 + 2];
            float l3 = acc[18 + a*4 + 3] + lb[a*4 + 3];
            locs[(size_t)i*4 + 0] = l0;
            locs[(size_t)i*4 + 1] = l1;
            locs[(size_t)i*4 + 2] = l2;
            locs[(size_t)i*4 + 3] = l3;
            float r  = ratios[a/3];
            float sc = scales[a%3];
            float hh = 16.f * sc * sqrtf(r);
            float ww = 16.f * sc * sqrtf(1.f/r);
            float a0 = sxp + 8.f - ww*0.5f;
            float a1 = syp + 8.f - hh*0.5f;
            float a2 = sxp + 8.f + ww*0.5f;
            float a3 = syp + 8.f + hh*0.5f;
            float aw = a2 - a0, ah = a3 - a1;
            float ax = a0 + 0.5f*aw, ay = a1 + 0.5f*ah;
            float cx = l0*aw + ax;
            float cy = l1*ah + ay;
            float wb = expf(l2)*aw;
            float hb = expf(l3)*ah;
            float x1 = fminf(fmaxf(cx - 0.5f*wb, 0.f), IW);
            float y1 = fminf(fmaxf(cy - 0.5f*hb, 0.f), IH);
            float x2 = fminf(fmaxf(cx + 0.5f*wb, 0.f), IW);
            float y2 = fminf(fmaxf(cy + 0.5f*hb, 0.f), IH);
            float* rr = g_roi + ((size_t)n*NA + (size_t)(p*9 + a))*4;
            rr[0] = x1; rr[1] = y1; rr[2] = x2; rr[3] = y2;
            bool valid = ((x2 - x1) >= 16.f) && ((y2 - y1) >= 16.f);
            g_key[(size_t)n*NSORT + p*9 + a] = valid ? fg : -INFINITY;
        }
    }
}

// ---------------- histogram select + single-block exact top sort ----------------
__device__ __forceinline__ bool sbefore(float ka, int ia, float kb, int ib)
{
    if (ka > kb) return true;
    if (ka < kb) return false;
    return ia < ib;
}

__device__ __forceinline__ void suffix_scan_1024(unsigned* tpart, int t)
{
    for (int off = 1; off < 1024; off <<= 1) {
        unsigned v = tpart[t] + ((t + off < 1024) ? tpart[t + off] : 0u);
        __syncthreads();
        tpart[t] = v;
        __syncthreads();
    }
}

#define SMEM_SEL (32768 + 32768 + 16384 + 4096)

__global__ __launch_bounds__(1024) void select_sort_kernel(void)
{
    extern __shared__ char smem[];
    float*    skey = (float*)smem;
    int*      sidx = (int*)(smem + 32768);
    unsigned* hist = (unsigned*)(smem + 65536);
    unsigned* tpart = (unsigned*)(smem + 81920);
    __shared__ unsigned sB1, sHi1, sCnt1, sTotal, sB2;
    __shared__ int sCnt;

    int n = blockIdx.x;
    int t = threadIdx.x;
    const float* keys = g_key + (size_t)n * NSORT;

    for (int b = t; b < 4096; b += 1024) hist[b] = 0u;
    if (t == 0) { sCnt = 0; sB1 = 0u; sHi1 = 0u; sCnt1 = 0u; sB2 = 0u; }
    __syncthreads();
    for (int i = t; i < NA; i += 1024) {
        unsigned u = __float_as_uint(keys[i]);
        if (!(u >> 31)) atomicAdd(&hist[u >> 20], 1u);
    }
    __syncthreads();
    { int b0 = t*4; tpart[t] = hist[b0] + hist[b0+1] + hist[b0+2] + hist[b0+3]; }
    __syncthreads();
    suffix_scan_1024(tpart, t);
    {
        unsigned beyond = (t < 1023) ? tpart[t+1] : 0u;
        int b0 = t * 4;
        unsigned h3 = hist[b0+3], h2 = hist[b0+2], h1 = hist[b0+1], h0 = hist[b0];
        unsigned hi3 = beyond, hi2 = beyond + h3, hi1v = hi2 + h2, hi0 = hi1v + h1;
        if (hi0  < PRE && PRE <= hi0  + h0) { sB1 = b0;   sHi1 = hi0;  sCnt1 = h0; }
        if (hi1v < PRE && PRE <= hi1v + h1) { sB1 = b0+1; sHi1 = hi1v; sCnt1 = h1; }
        if (hi2  < PRE && PRE <= hi2  + h2) { sB1 = b0+2; sHi1 = hi2;  sCnt1 = h2; }
        if (hi3  < PRE && PRE <= hi3  + h3) { sB1 = b0+3; sHi1 = hi3;  sCnt1 = h3; }
        if (t == 0) sTotal = tpart[0];
    }
    __syncthreads();

    unsigned TB;
    if (sTotal <= (unsigned)NSEL) {
        TB = 0u;
    } else if (sHi1 + sCnt1 <= (unsigned)NSEL) {
        TB = sB1 << 12;
    } else {
        unsigned B1 = sB1, R = (unsigned)PRE - sHi1;
        __syncthreads();
        for (int b = t; b < 4096; b += 1024) hist[b] = 0u;
        __syncthreads();
        for (int i = t; i < NA; i += 1024) {
            unsigned u = __float_as_uint(keys[i]);
            if (!(u >> 31) && (u >> 20) == B1) atomicAdd(&hist[(u >> 8) & 0xFFFu], 1u);
        }
        __syncthreads();
        { int b0 = t*4; tpart[t] = hist[b0] + hist[b0+1] + hist[b0+2] + hist[b0+3]; }
        __syncthreads();
        suffix_scan_1024(tpart, t);
        {
            unsigned beyond = (t < 1023) ? tpart[t+1] : 0u;
            int b0 = t * 4;
            unsigned h3 = hist[b0+3], h2 = hist[b0+2], h1 = hist[b0+1], h0 = hist[b0];
            unsigned hi3 = beyond, hi2 = beyond + h3, hi1v = hi2 + h2, hi0 = hi1v + h1;
            if (hi0  < R && R <= hi0  + h0) sB2 = b0;
            if (hi1v < R && R <= hi1v + h1) sB2 = b0+1;
            if (hi2  < R && R <= hi2  + h2) sB2 = b0+2;
            if (hi3  < R && R <= hi3  + h3) sB2 = b0+3;
        }
        __syncthreads();
        TB = (B1 << 12) | sB2;
    }
    __syncthreads();

    for (int i = t; i < NA; i += 1024) {
        float k = keys[i];
        unsigned u = __float_as_uint(k);
        if (!(u >> 31) && (u >> 8) >= TB) {
            int pos = atomicAdd(&sCnt, 1);
            if (pos < NSEL) { skey[pos] = k; sidx[pos] = i; }
        }
    }
    __syncthreads();
    int cnt = sCnt < NSEL ? sCnt : NSEL;
    for (int i = cnt + t; i < NSEL; i += 1024) { skey[i] = -INFINITY; sidx[i] = 0x7FFFFFFF; }
    __syncthreads();

    for (int k = 2; k <= NSEL; k <<= 1) {
        for (int j = k >> 1; j >= 1; j >>= 1) {
#pragma unroll
            for (int l = 0; l < 4; ++l) {
                int e = t + l * 1024;
                int i1 = ((e & ~(j-1)) << 1) | (e & (j-1));
                int i2 = i1 + j;
                bool up = ((i1 & k) == 0);
                float ka = skey[i1], kb = skey[i2];
                int ia = sidx[i1], ib = sidx[i2];
                if (sbefore(ka, ia, kb, ib) != up) {
                    skey[i1] = kb; sidx[i1] = ib; skey[i2] = ka; sidx[i2] = ia;
                }
            }
            __syncthreads();
        }
    }

    // emit sorted box arrays (rows 0..NROW-1) + validity words
    for (int i = t; i < NROW; i += 1024) {
        float k = skey[i];
        float x1 = 0.f, y1 = 0.f, x2 = 0.f, y2 = 0.f, ar = 0.f;
        if (i < PRE && isfinite(k)) {
            int id = sidx[i];
            const float* r = g_roi + ((size_t)n*NA + id)*4;
            x1 = r[0]; y1 = r[1]; x2 = r[2]; y2 = r[3];
            ar = (x2 - x1) * (y2 - y1);
        }
        g_sx1[n*NROW + i] = x1;
        g_sy1[n*NROW + i] = y1;
        g_sx2[n*NROW + i] = x2;
        g_sy2[n*NROW + i] = y2;
        g_sar[n*NROW + i] = ar;
    }
    if (t < NW) {
        unsigned long long w = 0ull;
        for (int k = 0; k < 64; ++k) {
            int i = t*64 + k;
            if (i < PRE && isfinite(skey[i])) w |= 1ull << k;
        }
        g_validw[n*NW + t] = w;
    }
}

// ---------------- NMS phase A: parallel IOU bitmask build ----------------
__device__ __forceinline__ bool iou_gt(float ax1, float ay1, float ax2, float ay2, float aa,
                                       float bx1, float by1, float bx2, float by2, float ba)
{
    float ix1 = fmaxf(ax1, bx1);
    float iy1 = fmaxf(ay1, by1);
    float ix2 = fminf(ax2, bx2);
    float iy2 = fminf(ay2, by2);
    float inter = fmaxf(ix2 - ix1, 0.f) * fmaxf(iy2 - iy1, 0.f);
    float iou = inter / (aa + ba - inter + 1e-9f);
    return iou > 0.7f;
}

__global__ __launch_bounds__(64) void nms_mask_kernel(void)
{
    int bxc = blockIdx.x;   // column chunk
    int byc = blockIdx.y;   // row chunk
    int n   = blockIdx.z;
    int t   = threadIdx.x;
    int i   = byc*64 + t;

    unsigned long long w = 0ull;
    if (bxc >= byc) {
        __shared__ float cx1[64], cy1[64], cx2[64], cy2[64], car[64];
        int j0 = bxc*64;
        cx1[t] = g_sx1[n*NROW + j0 + t];
        cy1[t] = g_sy1[n*NROW + j0 + t];
        cx2[t] = g_sx2[n*NROW + j0 + t];
        cy2[t] = g_sy2[n*NROW + j0 + t];
        car[t] = g_sar[n*NROW + j0 + t];
        __syncthreads();
        bool rv = (g_validw[n*NW + byc] >> t) & 1ull;
        if (rv) {
            float bx1 = g_sx1[n*NROW + i], by1 = g_sy1[n*NROW + i];
            float bx2 = g_sx2[n*NROW + i], by2 = g_sy2[n*NROW + i];
            float ba  = g_sar[n*NROW + i];
            for (int k = 0; k < 64; ++k) {
                int j = j0 + k;
                if (j > i && iou_gt(bx1, by1, bx2, by2, ba,
                                    cx1[k], cy1[k], cx2[k], cy2[k], car[k]))
                    w |= 1ull << k;
            }
        }
    }
    g_mask[((size_t)n*NROW + i)*NW + bxc] = w;
}

// ---------------- NMS phase B: serial greedy resolve over bitmasks + top-300 ----------------
__global__ __launch_bounds__(1024) void nms_resolve_kernel(float* __restrict__ out)
{
    __shared__ unsigned long long removed[NW];
    __shared__ unsigned long long keepw[NW];
    __shared__ int klist[64];
    __shared__ int kcnt_s;
    __shared__ int wsum[32];

    int n = blockIdx.x;
    int t = threadIdx.x;
    int lane = t & 31, wid = t >> 5;

    for (int w = t; w < NW; w += 1024) removed[w] = 0ull;
    for (int e = t; e < POST*4; e += 1024)
        out[OFF_ROIS + n*POST*4 + e] = 0.f;
    __syncthreads();

    for (int c = 0; c < NW; ++c) {
        if (wid == 0) {
            const unsigned long long* mcol = g_mask + ((size_t)n*NROW + c*64)*NW + c;
            unsigned long long d0 = mcol[(size_t)lane*NW];
            unsigned long long d1 = mcol[(size_t)(lane+32)*NW];
            unsigned long long cand = g_validw[n*NW + c] & ~removed[c];
            unsigned long long rm = 0ull, fk = 0ull;
            for (int k = 0; k < 64; ++k) {
                bool kp = ((cand >> k) & 1ull) && !((rm >> k) & 1ull);
                if (kp) {
                    fk |= 1ull << k;
                    unsigned long long src = (k < 32) ? d0 : d1;
                    unsigned lo = __shfl_sync(0xffffffffu, (unsigned)src, k & 31);
                    unsigned hi = __shfl_sync(0xffffffffu, (unsigned)(src >> 32), k & 31);
                    rm |= ((unsigned long long)hi << 32) | lo;
                }
            }
            if (lane == 0) { keepw[c] = fk; kcnt_s = (int)__popcll(fk); }
            if ((fk >> lane) & 1ull)
                klist[__popcll(fk & ((1ull << lane) - 1ull))] = c*64 + lane;
            int k2 = lane + 32;
            if ((fk >> k2) & 1ull)
                klist[__popcll(fk & ((1ull << k2) - 1ull))] = c*64 + k2;
        }
        __syncthreads();
        int kc = kcnt_s;
        if (kc > 0) {
            for (int w = t; w < NW; w += 1024) {
                unsigned long long acc = removed[w];
                for (int q = 0; q < kc; ++q)
                    acc |= g_mask[((size_t)n*NROW + klist[q])*NW + w];
                removed[w] = acc;
            }
        }
        __syncthreads();
    }

    // stable compaction: first POST kept rows in sorted order
    int base_i = t * 6;
    int loc[6];
    int lsum = 0;
#pragma unroll
    for (int q = 0; q < 6; ++q) {
        int ii = base_i + q;
        int v = (ii < PRE) ? (int)((keepw[ii >> 6] >> (ii & 63)) & 1ull) : 0;
        loc[q] = lsum;
        lsum += v;
    }
    int v = lsum;
    for (int o = 1; o < 32; o <<= 1) {
        int u = __shfl_up_sync(0xffffffffu, v, o);
        if (lane >= o) v += u;
    }
    if (lane == 31) wsum[wid] = v;
    __syncthreads();
    if (wid == 0) {
        int w2 = wsum[lane];
        for (int o = 1; o < 32; o <<= 1) {
            int u = __shfl_up_sync(0xffffffffu, w2, o);
            if (lane >= o) w2 += u;
        }
        wsum[lane] = w2;
    }
    __syncthreads();
    int excl = v - lsum + (wid > 0 ? wsum[wid-1] : 0);
#pragma unroll
    for (int q = 0; q < 6; ++q) {
        int ii = base_i + q;
        if (ii < PRE && ((keepw[ii >> 6] >> (ii & 63)) & 1ull)) {
            int r = excl + loc[q];
            if (r < POST) {
                float* o = out + OFF_ROIS + ((size_t)n*POST + r)*4;
                o[0] = g_sx1[n*NROW + ii];
                o[1] = g_sy1[n*NROW + ii];
                o[2] = g_sx2[n*NROW + ii];
                o[3] = g_sy2[n*NROW + ii];
            }
        }
    }
}

// ---------------- launch ----------------
extern "C" void kernel_launch(void* const* d_in, const int* in_sizes, int n_in,
                              void* d_out, int out_size)
{
    const float* x   = (const float*)d_in[0];
    const float* w1  = (const float*)d_in[1];
    const float* bc  = (const float*)d_in[2];
    const float* sw  = (const float*)d_in[3];
    const float* sbb = (const float*)d_in[4];
    const float* lw  = (const float*)d_in[5];
    const float* lb  = (const float*)d_in[6];
    const void*  ih  = d_in[7];
    const void*  iw  = d_in[8];
    float* out = (float*)d_out;

    static bool attr_done = false;
    if (!attr_done) {
        cudaFuncSetAttribute(conv_mma_kernel, cudaFuncAttributeMaxDynamicSharedMemorySize, SMEM_CONV);
        cudaFuncSetAttribute(heads_prep_kernel, cudaFuncAttributeMaxDynamicSharedMemorySize, 512*54*4);
        cudaFuncSetAttribute(select_sort_kernel, cudaFuncAttributeMaxDynamicSharedMemorySize, SMEM_SEL);
        attr_done = true;
    }

    fuse1_kernel<<<(N_FUSE1 + 255)/256, 256>>>(w1, out);
    xpose_kernel<<<dim3(60, 16, BATCH), 256>>>(x);
    conv_mma_kernel<<<dim3(CO/128, PPAD/64, BATCH), 256, SMEM_CONV>>>(bc);
    heads_prep_kernel<<<dim3((P + 255)/256, BATCH), 256, 512*54*4>>>(sw, sbb, lw, lb, out, ih, iw);
    select_sort_kernel<<<BATCH, 1024, SMEM_SEL>>>();
    nms_mask_kernel<<<dim3(NW, NW, BATCH), 64>>>();
    nms_resolve_kernel<<<BATCH, 1024>>>(out);
}